// round 16
// baseline (speedup 1.0000x reference)
#include <cuda_runtime.h>
#include <cuda_fp16.h>

#define N_NODES 50000
#define N_EDGES 800000

// ---------------- scratch (static device globals; no allocation) ----------------
static __device__ __half g_a1  [(size_t)N_NODES * 256];   // [agg (RED target) | fp16(x)]
static __device__ __half g_agg216[(size_t)N_NODES * 128];
static __device__ float  g_deg [N_NODES];
static __device__ __half g_y1  [(size_t)N_NODES * 256];
static __device__ __half g_z1  [(size_t)N_NODES * 256];
static __device__ __half g_t1  [(size_t)N_NODES * 512];
static __device__ __half g_h2  [(size_t)N_NODES * 256];
static __device__ __half g_p16 [(size_t)N_NODES * 128];   // h2@Wl2 (scatter source)
static __device__ __half g_r16 [(size_t)N_NODES * 128];   // h2@Wr2 (root term)
static __device__ __half g_y2  [(size_t)N_NODES * 128];
static __device__ __half g_z2  [(size_t)N_NODES * 128];
static __device__ __half g_t3  [(size_t)N_NODES * 256];
// transposed fp16 weights [n][k]
static __device__ __half g_bt1 [256 * 256];
static __device__ __half g_w1t [512 * 256];
static __device__ __half g_w2t [256 * 512];
static __device__ __half g_blr2[256 * 256];   // rows 0-127: Wl2t, 128-255: Wr2t
static __device__ __half g_w3t [256 * 128];
static __device__ __half g_w4t [128 * 256];
static __device__ double g_sums[4];
static __device__ int    g_is64;

// ---------------- prep (data half): is64 + sums + zeroes + x->fp16 ----------------
#define SEG_A1Z (N_NODES * 16)
#define SEG_XC  (N_NODES * 16)
#define SEG_A2Z (N_NODES * 16)
#define SEG_DG  (N_NODES / 4)
#define PREPD_TOTAL (SEG_A1Z + SEG_XC + SEG_A2Z + SEG_DG)

__global__ void k_prep_data(const unsigned long long* __restrict__ ei,
                            const float* __restrict__ x, __half* __restrict__ a1,
                            uint4* __restrict__ agg216z, float4* __restrict__ deg4)
{
    int i = blockIdx.x * blockDim.x + threadIdx.x;
    if (i == 0) {
        int ok = 1;
#pragma unroll
        for (int j = 0; j < 16; j++)
            ok &= ((ei[j] >> 32) == 0ull) ? 1 : 0;
        g_is64 = ok;
        g_sums[0] = 0.0; g_sums[1] = 0.0; g_sums[2] = 0.0; g_sums[3] = 0.0;
    }
    if (i < SEG_A1Z) {
        int row = i >> 4, c8 = (i & 15) * 8;
        *reinterpret_cast<uint4*>(a1 + (size_t)row * 256 + c8) = make_uint4(0u, 0u, 0u, 0u);
        return;
    }
    i -= SEG_A1Z;
    if (i < SEG_XC) {
        int row = i >> 4, c8 = (i & 15) * 8;
        float4 v0 = *reinterpret_cast<const float4*>(x + (size_t)row * 128 + c8);
        float4 v1 = *reinterpret_cast<const float4*>(x + (size_t)row * 128 + c8 + 4);
        __half2 h0 = __floats2half2_rn(v0.x, v0.y);
        __half2 h1 = __floats2half2_rn(v0.z, v0.w);
        __half2 h2 = __floats2half2_rn(v1.x, v1.y);
        __half2 h3 = __floats2half2_rn(v1.z, v1.w);
        uint4 u = make_uint4(*reinterpret_cast<unsigned*>(&h0), *reinterpret_cast<unsigned*>(&h1),
                             *reinterpret_cast<unsigned*>(&h2), *reinterpret_cast<unsigned*>(&h3));
        *reinterpret_cast<uint4*>(a1 + (size_t)row * 256 + 128 + c8) = u;
        return;
    }
    i -= SEG_XC;
    if (i < SEG_A2Z) { agg216z[i] = make_uint4(0u, 0u, 0u, 0u); return; }
    i -= SEG_A2Z;
    if (i < SEG_DG)  { deg4[i] = make_float4(0.f, 0.f, 0.f, 0.f); }
}

// ---------------- prep (weights half) ----------------
#define PREPW_TOTAL (32768 * 6 + 131072 * 2)
__global__ void k_prep_w(const float* __restrict__ Wl1, const float* __restrict__ Wr1,
                         const float* __restrict__ W1,  const float* __restrict__ W2,
                         const float* __restrict__ Wl2, const float* __restrict__ Wr2,
                         const float* __restrict__ W3,  const float* __restrict__ W4,
                         __half* __restrict__ bt1, __half* __restrict__ w1t,
                         __half* __restrict__ w2t, __half* __restrict__ blr2,
                         __half* __restrict__ w3t, __half* __restrict__ w4t)
{
    int i = blockIdx.x * blockDim.x + threadIdx.x;
    if (i < 32768)  { int k = i / 256, n = i % 256; bt1[n * 256 + k] = __float2half_rn(Wl1[i]); return; }
    i -= 32768;
    if (i < 32768)  { int k = i / 256, n = i % 256; bt1[n * 256 + k + 128] = __float2half_rn(Wr1[i]); return; }
    i -= 32768;
    if (i < 131072) { int k = i / 512, n = i % 512; w1t[n * 256 + k] = __float2half_rn(W1[i]); return; }
    i -= 131072;
    if (i < 131072) { int k = i / 256, n = i % 256; w2t[n * 512 + k] = __float2half_rn(W2[i]); return; }
    i -= 131072;
    if (i < 32768)  { int k = i / 128, n = i % 128; blr2[n * 256 + k] = __float2half_rn(Wl2[i]); return; }
    i -= 32768;
    if (i < 32768)  { int k = i / 128, n = i % 128; blr2[(n + 128) * 256 + k] = __float2half_rn(Wr2[i]); return; }
    i -= 32768;
    if (i < 32768)  { int k = i / 256, n = i % 256; w3t[n * 128 + k] = __float2half_rn(W3[i]); return; }
    i -= 32768;
    if (i < 32768)  { int k = i / 128, n = i % 128; w4t[n * 256 + k] = __float2half_rn(W4[i]); }
}

// ---------------- edge scatter: fp16x2 vector-RED, 16 lanes/edge ----------------
__global__ void k_scatter_h(const void* __restrict__ ei, const __half* __restrict__ feat,
                            int fstride, __half* __restrict__ agg, int dstride,
                            float* __restrict__ deg, int addDeg)
{
    int gt   = blockIdx.x * blockDim.x + threadIdx.x;
    int edge = gt >> 4;
    int hl   = gt & 15;
    if (edge >= N_EDGES) return;

    long long s, d;
    if (g_is64) {
        const long long* p = (const long long*)ei;
        s = p[edge]; d = p[N_EDGES + edge];
    } else {
        const int* p = (const int*)ei;
        s = p[edge];  d = p[N_EDGES + edge];
    }

    uint4 v = *reinterpret_cast<const uint4*>(feat + (size_t)s * fstride + hl * 8);
    __half* dp = agg + (size_t)d * dstride + hl * 8;
    asm volatile("red.global.add.noftz.v4.f16x2 [%0], {%1,%2,%3,%4};"
                 :: "l"(dp), "r"(v.x), "r"(v.y), "r"(v.z), "r"(v.w) : "memory");
    if (addDeg && hl == 0) atomicAdd(deg + d, 1.0f);
}

// ---------------- LN+ReLU: per-thread float stats, 8 halves/thread ----------------
__global__ void k_lnrelu(const __half* __restrict__ src, __half* __restrict__ dst,
                         const float* __restrict__ w, const float* __restrict__ b,
                         int Cmask, int statOff, float invcnt, int total8)
{
    int idx = blockIdx.x * blockDim.x + threadIdx.x;
    if (idx >= total8) return;
    float s0 = (float)g_sums[statOff];
    float s1 = (float)g_sums[statOff + 1];
    float mu = s0 * invcnt;
    float rs = rsqrtf(fmaf(s1, invcnt, -mu * mu) + 1e-5f);
    int c = (idx * 8) & Cmask;
    uint4 u = reinterpret_cast<const uint4*>(src)[idx];
    float2 v0 = __half22float2(*reinterpret_cast<const __half2*>(&u.x));
    float2 v1 = __half22float2(*reinterpret_cast<const __half2*>(&u.y));
    float2 v2 = __half22float2(*reinterpret_cast<const __half2*>(&u.z));
    float2 v3 = __half22float2(*reinterpret_cast<const __half2*>(&u.w));
    float4 wa = *reinterpret_cast<const float4*>(w + c);
    float4 wb = *reinterpret_cast<const float4*>(w + c + 4);
    float4 ba = *reinterpret_cast<const float4*>(b + c);
    float4 bb = *reinterpret_cast<const float4*>(b + c + 4);
    __half2 o0 = __floats2half2_rn(fmaxf((v0.x - mu) * rs * wa.x + ba.x, 0.f),
                                   fmaxf((v0.y - mu) * rs * wa.y + ba.y, 0.f));
    __half2 o1 = __floats2half2_rn(fmaxf((v1.x - mu) * rs * wa.z + ba.z, 0.f),
                                   fmaxf((v1.y - mu) * rs * wa.w + ba.w, 0.f));
    __half2 o2 = __floats2half2_rn(fmaxf((v2.x - mu) * rs * wb.x + bb.x, 0.f),
                                   fmaxf((v2.y - mu) * rs * wb.y + bb.y, 0.f));
    __half2 o3 = __floats2half2_rn(fmaxf((v3.x - mu) * rs * wb.z + bb.z, 0.f),
                                   fmaxf((v3.y - mu) * rs * wb.w + bb.w, 0.f));
    uint4 o = make_uint4(*reinterpret_cast<unsigned*>(&o0), *reinterpret_cast<unsigned*>(&o1),
                         *reinterpret_cast<unsigned*>(&o2), *reinterpret_cast<unsigned*>(&o3));
    reinterpret_cast<uint4*>(dst)[idx] = o;
}

// ---------------- FP16 tensor-core GEMM, 3-stage cp.async ring, XOR swizzle ----------------
#define TILE_BYTES (128 * 128)
#define STAGE_BYTES (2 * TILE_BYTES)
#define NSTAGE 3
#define GEMM_SMEM_BYTES (NSTAGE * STAGE_BYTES)

__device__ __forceinline__ void ldsm4(unsigned* r, unsigned addr)
{
    asm volatile("ldmatrix.sync.aligned.m8n8.x4.shared.b16 {%0,%1,%2,%3}, [%4];"
                 : "=r"(r[0]), "=r"(r[1]), "=r"(r[2]), "=r"(r[3]) : "r"(addr));
}

__device__ __forceinline__ void mma_f16(float* c, const unsigned* a,
                                        unsigned b0, unsigned b1)
{
    asm volatile(
        "mma.sync.aligned.m16n8k16.row.col.f32.f16.f16.f32 "
        "{%0,%1,%2,%3}, {%4,%5,%6,%7}, {%8,%9}, {%0,%1,%2,%3};\n"
        : "+f"(c[0]), "+f"(c[1]), "+f"(c[2]), "+f"(c[3])
        : "r"(a[0]), "r"(a[1]), "r"(a[2]), "r"(a[3]), "r"(b0), "r"(b1));
}

template <bool RELU, bool BIAS, bool STATS, bool HOUT, bool MS>
__global__ void __launch_bounds__(256, 2)
k_gemm(const __half* __restrict__ A, const __half* __restrict__ Bt,
       const float* __restrict__ bias, float* __restrict__ C,
       int M, int Nc, int K, double* __restrict__ sums,
       const float* __restrict__ deg)
{
    extern __shared__ __align__(16) unsigned char dsm[];
    __shared__ double sred[256];

    const int tid  = threadIdx.x;
    const int lane = tid & 31;
    const int wid  = tid >> 5;
    const int g    = lane >> 2;
    const int t4   = lane & 3;
    const int warpM = (wid >> 2) * 64;
    const int warpN = (wid & 3) * 32;
    const int rowBase = blockIdx.y * 128;
    const int colBase = blockIdx.x * 128;

    float acc[4][4][4];
#pragma unroll
    for (int i = 0; i < 4; i++)
#pragma unroll
        for (int j = 0; j < 4; j++)
#pragma unroll
            for (int k = 0; k < 4; k++) acc[i][j][k] = 0.f;

    float inv0[4], inv8[4];
    if (MS) {
#pragma unroll
        for (int mt = 0; mt < 4; mt++) {
            int r0 = rowBase + warpM + mt * 16 + g;
            inv0[mt] = (r0 < M)     ? 1.0f / fmaxf(deg[r0], 1.0f)     : 1.0f;
            inv8[mt] = (r0 + 8 < M) ? 1.0f / fmaxf(deg[r0 + 8], 1.0f) : 1.0f;
        }
    }

    const int fR  = tid >> 1;
    const int fXr = fR & 7;
    const int fC0 = (tid & 1) * 4;
    const unsigned smBase = (unsigned)__cvta_generic_to_shared(dsm);
    const unsigned aRowDst = smBase + (unsigned)(fR * 128);
    const unsigned bRowDst = smBase + (unsigned)(TILE_BYTES + fR * 128);
    const bool aOk = (rowBase + fR) < M;
    const int  aSz = aOk ? 16 : 0;
    const __half* aSrcRow = A + (size_t)(aOk ? rowBase + fR : 0) * K + fC0 * 8;
    const __half* bSrcRow = Bt + (size_t)(colBase + fR) * K + fC0 * 8;

    const int aRowL = warpM + (lane & 7) + ((lane >> 3) & 1) * 8;
    const unsigned aRow0 = smBase + (unsigned)(aRowL * 128);
    const int xrA = lane & 7;
    const int cA  = (lane >> 4) & 1;
    const int bRowL = warpN + (lane & 7);
    const unsigned bRow0 = smBase + (unsigned)(TILE_BYTES + bRowL * 128);
    const int xrB = lane & 7;
    const int cB  = lane >> 3;

    auto FILL = [&](int s, int k0) {
        unsigned off = (unsigned)(s * STAGE_BYTES);
        const __half* as = aSrcRow + k0;
        const __half* bs = bSrcRow + k0;
#pragma unroll
        for (int j = 0; j < 4; j++) {
            unsigned dA = aRowDst + off + (unsigned)((((fC0 + j) ^ fXr)) << 4);
            asm volatile("cp.async.cg.shared.global [%0], [%1], 16, %2;"
                         :: "r"(dA), "l"(as + j * 8), "r"(aSz) : "memory");
        }
#pragma unroll
        for (int j = 0; j < 4; j++) {
            unsigned dB = bRowDst + off + (unsigned)((((fC0 + j) ^ fXr)) << 4);
            asm volatile("cp.async.cg.shared.global [%0], [%1], 16;"
                         :: "r"(dB), "l"(bs + j * 8) : "memory");
        }
        asm volatile("cp.async.commit_group;" ::: "memory");
    };

    auto MMA = [&](int s) {
        unsigned off = (unsigned)(s * STAGE_BYTES);
#pragma unroll
        for (int kbp = 0; kbp < 2; kbp++) {
            unsigned bf[4][4];
#pragma unroll
            for (int nt = 0; nt < 4; nt++)
                ldsm4(bf[nt], bRow0 + off + (unsigned)(nt * 8 * 128)
                              + (unsigned)(((cB + 4 * kbp) ^ xrB) << 4));
#pragma unroll
            for (int kk = 0; kk < 2; kk++) {
                int kb = kbp * 2 + kk;
                unsigned af[4][4];
#pragma unroll
                for (int mt = 0; mt < 4; mt++)
                    ldsm4(af[mt], aRow0 + off + (unsigned)(mt * 16 * 128)
                                  + (unsigned)(((cA + 2 * kb) ^ xrA) << 4));
#pragma unroll
                for (int nt = 0; nt < 4; nt++)
#pragma unroll
                    for (int mt = 0; mt < 4; mt++)
                        mma_f16(acc[mt][nt], af[mt], bf[nt][kk * 2], bf[nt][kk * 2 + 1]);
            }
        }
    };

    const int T = K >> 6;
    FILL(0, 0);
    if (T > 1) FILL(1, 64);
    int curS = 0;
    int fillS = (T > 1) ? 2 : 1;
    if (fillS >= NSTAGE) fillS -= NSTAGE;
    for (int i = 0; i < T; i++) {
        if (i + 1 < T) { asm volatile("cp.async.wait_group 1;" ::: "memory"); }
        else           { asm volatile("cp.async.wait_group 0;" ::: "memory"); }
        __syncthreads();
        if (i + 2 < T) {
            FILL(fillS, (i + 2) * 64);
            if (++fillS == NSTAGE) fillS = 0;
        }
        MMA(curS);
        if (MS && i == 1) {
#pragma unroll
            for (int mt = 0; mt < 4; mt++)
#pragma unroll
                for (int nt = 0; nt < 4; nt++) {
                    acc[mt][nt][0] *= inv0[mt];
                    acc[mt][nt][1] *= inv0[mt];
                    acc[mt][nt][2] *= inv8[mt];
                    acc[mt][nt][3] *= inv8[mt];
                }
        }
        if (++curS == NSTAGE) curS = 0;
    }

    // ---- epilogue ----
    __half* Ch = reinterpret_cast<__half*>(C);
    double s1 = 0.0, s2 = 0.0;
#pragma unroll
    for (int nt = 0; nt < 4; nt++) {
        int col = colBase + warpN + nt * 8 + 2 * t4;
        float2 bv = make_float2(0.f, 0.f);
        if (BIAS) bv = *reinterpret_cast<const float2*>(bias + col);
#pragma unroll
        for (int mt = 0; mt < 4; mt++) {
            int r0 = rowBase + warpM + mt * 16 + g;
            float c0 = acc[mt][nt][0] + bv.x;
            float c1 = acc[mt][nt][1] + bv.y;
            float c2 = acc[mt][nt][2] + bv.x;
            float c3 = acc[mt][nt][3] + bv.y;
            if (RELU) {
                c0 = fmaxf(c0, 0.f); c1 = fmaxf(c1, 0.f);
                c2 = fmaxf(c2, 0.f); c3 = fmaxf(c3, 0.f);
            }
            if (r0 < M) {
                if (HOUT)
                    *reinterpret_cast<__half2*>(Ch + (size_t)r0 * Nc + col) = __floats2half2_rn(c0, c1);
                else
                    *reinterpret_cast<float2*>(C + (size_t)r0 * Nc + col) = make_float2(c0, c1);
                if (STATS) { s1 += (double)c0 + (double)c1;
                             s2 += (double)c0 * c0 + (double)c1 * c1; }
            }
            if (r0 + 8 < M) {
                if (HOUT)
                    *reinterpret_cast<__half2*>(Ch + (size_t)(r0 + 8) * Nc + col) = __floats2half2_rn(c2, c3);
                else
                    *reinterpret_cast<float2*>(C + (size_t)(r0 + 8) * Nc + col) = make_float2(c2, c3);
                if (STATS) { s1 += (double)c2 + (double)c3;
                             s2 += (double)c2 * c2 + (double)c3 * c3; }
            }
        }
    }

    if (STATS) {
        sred[tid] = s1; __syncthreads();
        for (int o = 128; o > 0; o >>= 1) { if (tid < o) sred[tid] += sred[tid + o]; __syncthreads(); }
        if (tid == 0) atomicAdd(&sums[0], sred[0]);
        __syncthreads();
        sred[tid] = s2; __syncthreads();
        for (int o = 128; o > 0; o >>= 1) { if (tid < o) sred[tid] += sred[tid + o]; __syncthreads(); }
        if (tid == 0) atomicAdd(&sums[1], sred[0]);
    }
}

// ---------------- conv2 combine: 8 halves/thread (separate r16 buffer) ----------------
__global__ void k_y2(const __half* __restrict__ agg216, const __half* __restrict__ r16,
                     const float* __restrict__ bl2, const float* __restrict__ deg,
                     __half* __restrict__ y2)
{
    __shared__ double sred[256];
    double s1 = 0.0, s2 = 0.0;
    const int n8 = N_NODES * 16;
    for (int idx = blockIdx.x * blockDim.x + threadIdx.x; idx < n8; idx += gridDim.x * blockDim.x) {
        int i = idx >> 4, c = (idx & 15) * 8;
        float inv = 1.0f / fmaxf(deg[i], 1.0f);
        uint4 au = *reinterpret_cast<const uint4*>(agg216 + (size_t)i * 128 + c);
        uint4 ru = *reinterpret_cast<const uint4*>(r16 + (size_t)i * 128 + c);
        const unsigned* aw = &au.x;
        const unsigned* rw = &ru.x;
        unsigned ow[4];
#pragma unroll
        for (int q = 0; q < 4; q++) {
            float2 a = __half22float2(*reinterpret_cast<const __half2*>(&aw[q]));
            float2 r = __half22float2(*reinterpret_cast<const __half2*>(&rw[q]));
            float2 bq = *reinterpret_cast<const float2*>(bl2 + c + q * 2);
            float y0 = a.x * inv + bq.x + r.x;
            float y1 = a.y * inv + bq.y + r.y;
            __half2 h = __floats2half2_rn(y0, y1);
            ow[q] = *reinterpret_cast<unsigned*>(&h);
            s1 += (double)y0 + (double)y1;
            s2 += (double)y0 * y0 + (double)y1 * y1;
        }
        *reinterpret_cast<uint4*>(y2 + (size_t)i * 128 + c) =
            make_uint4(ow[0], ow[1], ow[2], ow[3]);
    }
    int tid = threadIdx.x;
    sred[tid] = s1; __syncthreads();
    for (int o = 128; o > 0; o >>= 1) { if (tid < o) sred[tid] += sred[tid + o]; __syncthreads(); }
    if (tid == 0) atomicAdd(&g_sums[2], sred[0]);
    __syncthreads();
    sred[tid] = s2; __syncthreads();
    for (int o = 128; o > 0; o >>= 1) { if (tid < o) sred[tid] += sred[tid + o]; __syncthreads(); }
    if (tid == 0) atomicAdd(&g_sums[3], sred[0]);
}

// ---------------- launch (fork-join dual-stream, graph-capturable) ----------------
extern "C" void kernel_launch(void* const* d_in, const int* in_sizes, int n_in,
                              void* d_out, int out_size)
{
    const float* x    = (const float*)d_in[0];
    const void*  ei   =               d_in[1];
    const float* Wl1  = (const float*)d_in[2];
    const float* bl1  = (const float*)d_in[3];
    const float* Wr1  = (const float*)d_in[4];
    const float* ln1w = (const float*)d_in[5];
    const float* ln1b = (const float*)d_in[6];
    const float* W1   = (const float*)d_in[7];
    const float* b1   = (const float*)d_in[8];
    const float* W2   = (const float*)d_in[9];
    const float* b2   = (const float*)d_in[10];
    const float* Wl2  = (const float*)d_in[11];
    const float* bl2  = (const float*)d_in[12];
    const float* Wr2  = (const float*)d_in[13];
    const float* ln2w = (const float*)d_in[14];
    const float* ln2b = (const float*)d_in[15];
    const float* W3   = (const float*)d_in[16];
    const float* b3   = (const float*)d_in[17];
    const float* W4   = (const float*)d_in[18];
    const float* b4   = (const float*)d_in[19];
    float* out = (float*)d_out;

    float *deg;
    __half *a1, *agg216, *y1, *z1, *t1, *h2, *p16, *r16, *y2, *z2, *t3;
    __half *bt1, *w1t, *w2t, *blr2, *w3t, *w4t;
    double* sums;
    cudaGetSymbolAddress((void**)&a1,     g_a1);
    cudaGetSymbolAddress((void**)&agg216, g_agg216);
    cudaGetSymbolAddress((void**)&deg,  g_deg);
    cudaGetSymbolAddress((void**)&y1,   g_y1);
    cudaGetSymbolAddress((void**)&z1,   g_z1);
    cudaGetSymbolAddress((void**)&t1,   g_t1);
    cudaGetSymbolAddress((void**)&h2,   g_h2);
    cudaGetSymbolAddress((void**)&p16,  g_p16);
    cudaGetSymbolAddress((void**)&r16,  g_r16);
    cudaGetSymbolAddress((void**)&y2,   g_y2);
    cudaGetSymbolAddress((void**)&z2,   g_z2);
    cudaGetSymbolAddress((void**)&t3,   g_t3);
    cudaGetSymbolAddress((void**)&bt1,  g_bt1);
    cudaGetSymbolAddress((void**)&w1t,  g_w1t);
    cudaGetSymbolAddress((void**)&w2t,  g_w2t);
    cudaGetSymbolAddress((void**)&blr2, g_blr2);
    cudaGetSymbolAddress((void**)&w3t,  g_w3t);
    cudaGetSymbolAddress((void**)&w4t,  g_w4t);
    cudaGetSymbolAddress((void**)&sums, g_sums);
    __half* wl2t = blr2;
    __half* wr2t = blr2 + 128 * 256;

    // one-time resources (host-side handles; no device allocation)
    static cudaStream_t sB = nullptr;
    static cudaEvent_t evF = nullptr, evW = nullptr, evH = nullptr, evR = nullptr;
    if (!sB) {
        cudaStreamCreateWithFlags(&sB, cudaStreamNonBlocking);
        cudaEventCreateWithFlags(&evF, cudaEventDisableTiming);
        cudaEventCreateWithFlags(&evW, cudaEventDisableTiming);
        cudaEventCreateWithFlags(&evH, cudaEventDisableTiming);
        cudaEventCreateWithFlags(&evR, cudaEventDisableTiming);
        cudaFuncSetAttribute(k_gemm<false, true,  true,  true,  true >, cudaFuncAttributeMaxDynamicSharedMemorySize, GEMM_SMEM_BYTES);
        cudaFuncSetAttribute(k_gemm<true,  true,  false, true,  false>, cudaFuncAttributeMaxDynamicSharedMemorySize, GEMM_SMEM_BYTES);
        cudaFuncSetAttribute(k_gemm<false, false, false, true,  false>, cudaFuncAttributeMaxDynamicSharedMemorySize, GEMM_SMEM_BYTES);
        cudaFuncSetAttribute(k_gemm<false, true,  false, false, false>, cudaFuncAttributeMaxDynamicSharedMemorySize, GEMM_SMEM_BYTES);
    }

    const int M = N_NODES;
    const unsigned gy = (M + 127) / 128;
    const int scatterBlocks = (N_EDGES * 16 + 255) / 256;

    // --- fork: weights on sB, data prep + scatter on default ---
    cudaEventRecord(evF, 0);
    cudaStreamWaitEvent(sB, evF, 0);
    k_prep_w<<<(PREPW_TOTAL + 255) / 256, 256, 0, sB>>>(Wl1, Wr1, W1, W2, Wl2, Wr2, W3, W4,
                                                        bt1, w1t, w2t, blr2, w3t, w4t);
    cudaEventRecord(evW, sB);

    k_prep_data<<<(PREPD_TOTAL + 255) / 256, 256>>>((const unsigned long long*)ei,
                                                    x, a1, (uint4*)agg216, (float4*)deg);
    k_scatter_h<<<scatterBlocks, 256>>>(ei, a1 + 128, 256, a1, 256, deg, 1);
    cudaStreamWaitEvent(0, evW, 0);   // join: GEMM1 needs weights

    // --- conv1 ---
    k_gemm<false, true, true, true, true><<<dim3(2, gy), 256, GEMM_SMEM_BYTES>>>(
        a1, bt1, bl1, (float*)y1, M, 256, 256, sums, deg);
    k_lnrelu<<<(N_NODES * 32 + 255) / 256, 256>>>(y1, z1, ln1w, ln1b, 255, 0,
                                                  1.0f / (float)(N_NODES * 256.0), N_NODES * 32);
    k_gemm<true, true, false, true, false><<<dim3(4, gy), 256, GEMM_SMEM_BYTES>>>(
        z1, w1t, b1, (float*)t1, M, 512, 256, nullptr, nullptr);
    k_gemm<true, true, false, true, false><<<dim3(2, gy), 256, GEMM_SMEM_BYTES>>>(
        t1, w2t, b2, (float*)h2, M, 256, 512, nullptr, nullptr);

    // --- conv2: fork r-projection onto sB, overlap with p-projection + scatter ---
    cudaEventRecord(evH, 0);          // h2 ready
    cudaStreamWaitEvent(sB, evH, 0);
    k_gemm<false, false, false, true, false><<<dim3(1, gy), 256, GEMM_SMEM_BYTES, sB>>>(
        h2, wr2t, nullptr, (float*)r16, M, 128, 256, nullptr, nullptr);
    cudaEventRecord(evR, sB);

    k_gemm<false, false, false, true, false><<<dim3(1, gy), 256, GEMM_SMEM_BYTES>>>(
        h2, wl2t, nullptr, (float*)p16, M, 128, 256, nullptr, nullptr);
    k_scatter_h<<<scatterBlocks, 256>>>(ei, p16, 128, agg216, 128, deg, 0);
    cudaStreamWaitEvent(0, evR, 0);   // join: k_y2 needs r16

    k_y2<<<1024, 256>>>(agg216, r16, bl2, deg, y2);
    k_lnrelu<<<(N_NODES * 16 + 255) / 256, 256>>>(y2, z2, ln2w, ln2b, 127, 2,
                                                  1.0f / (float)(N_NODES * 128.0), N_NODES * 16);
    k_gemm<true, true, false, true, false><<<dim3(2, gy), 256, GEMM_SMEM_BYTES>>>(
        z2, w3t, b3, (float*)t3, M, 256, 128, nullptr, nullptr);
    k_gemm<false, true, false, false, false><<<dim3(1, gy), 256, GEMM_SMEM_BYTES>>>(
        t3, w4t, b4, out, M, 128, 256, nullptr, nullptr);
}

// round 17
// speedup vs baseline: 1.2936x; 1.2936x over previous
#include <cuda_runtime.h>
#include <cuda_fp16.h>

#define N_NODES 50000
#define N_EDGES 800000

// ---------------- scratch (static device globals; no allocation) ----------------
static __device__ __half g_a1  [(size_t)N_NODES * 256];   // [agg (RED target) | fp16(x)]
static __device__ __half g_agg216[(size_t)N_NODES * 128];
static __device__ float  g_deg [N_NODES];
static __device__ __half g_y1  [(size_t)N_NODES * 256];
static __device__ __half g_z1  [(size_t)N_NODES * 256];
static __device__ __half g_t1  [(size_t)N_NODES * 512];
static __device__ __half g_h2  [(size_t)N_NODES * 256];
static __device__ __half g_pr16[(size_t)N_NODES * 256];   // [p | r]
static __device__ __half g_y2  [(size_t)N_NODES * 128];
static __device__ __half g_z2  [(size_t)N_NODES * 128];
static __device__ __half g_t3  [(size_t)N_NODES * 256];
// transposed fp16 weights [n][k]
static __device__ __half g_bt1 [256 * 256];
static __device__ __half g_w1t [512 * 256];
static __device__ __half g_w2t [256 * 512];
static __device__ __half g_blr2[256 * 256];
static __device__ __half g_w3t [256 * 128];
static __device__ __half g_w4t [128 * 256];
static __device__ double g_sums[4];
static __device__ int    g_is64;

// ---------------- ONE prep kernel ----------------
#define SEG_A1Z (N_NODES * 16)
#define SEG_XC  (N_NODES * 16)
#define SEG_A2Z (N_NODES * 16)
#define SEG_DG  (N_NODES / 4)
#define SEG_WT  (32768 * 6 + 131072 * 2)
#define PREP_TOTAL (SEG_A1Z + SEG_XC + SEG_A2Z + SEG_DG + SEG_WT)

__global__ void k_prep(const unsigned long long* __restrict__ ei,
                       const float* __restrict__ x, __half* __restrict__ a1,
                       uint4* __restrict__ agg216z, float4* __restrict__ deg4,
                       const float* __restrict__ Wl1, const float* __restrict__ Wr1,
                       const float* __restrict__ W1,  const float* __restrict__ W2,
                       const float* __restrict__ Wl2, const float* __restrict__ Wr2,
                       const float* __restrict__ W3,  const float* __restrict__ W4,
                       __half* __restrict__ bt1, __half* __restrict__ w1t,
                       __half* __restrict__ w2t, __half* __restrict__ blr2,
                       __half* __restrict__ w3t, __half* __restrict__ w4t)
{
    int i = blockIdx.x * blockDim.x + threadIdx.x;
    if (i == 0) {
        int ok = 1;
#pragma unroll
        for (int j = 0; j < 16; j++)
            ok &= ((ei[j] >> 32) == 0ull) ? 1 : 0;
        g_is64 = ok;
        g_sums[0] = 0.0; g_sums[1] = 0.0; g_sums[2] = 0.0; g_sums[3] = 0.0;
    }
    if (i < SEG_A1Z) {
        int row = i >> 4, c8 = (i & 15) * 8;
        *reinterpret_cast<uint4*>(a1 + (size_t)row * 256 + c8) = make_uint4(0u, 0u, 0u, 0u);
        return;
    }
    i -= SEG_A1Z;
    if (i < SEG_XC) {
        int row = i >> 4, c8 = (i & 15) * 8;
        float4 v0 = *reinterpret_cast<const float4*>(x + (size_t)row * 128 + c8);
        float4 v1 = *reinterpret_cast<const float4*>(x + (size_t)row * 128 + c8 + 4);
        __half2 h0 = __floats2half2_rn(v0.x, v0.y);
        __half2 h1 = __floats2half2_rn(v0.z, v0.w);
        __half2 h2 = __floats2half2_rn(v1.x, v1.y);
        __half2 h3 = __floats2half2_rn(v1.z, v1.w);
        uint4 u = make_uint4(*reinterpret_cast<unsigned*>(&h0), *reinterpret_cast<unsigned*>(&h1),
                             *reinterpret_cast<unsigned*>(&h2), *reinterpret_cast<unsigned*>(&h3));
        *reinterpret_cast<uint4*>(a1 + (size_t)row * 256 + 128 + c8) = u;
        return;
    }
    i -= SEG_XC;
    if (i < SEG_A2Z) { agg216z[i] = make_uint4(0u, 0u, 0u, 0u); return; }
    i -= SEG_A2Z;
    if (i < SEG_DG)  { deg4[i] = make_float4(0.f, 0.f, 0.f, 0.f); return; }
    i -= SEG_DG;
    if (i < 32768)  { int k = i / 256, n = i % 256; bt1[n * 256 + k] = __float2half_rn(Wl1[i]); return; }
    i -= 32768;
    if (i < 32768)  { int k = i / 256, n = i % 256; bt1[n * 256 + k + 128] = __float2half_rn(Wr1[i]); return; }
    i -= 32768;
    if (i < 131072) { int k = i / 512, n = i % 512; w1t[n * 256 + k] = __float2half_rn(W1[i]); return; }
    i -= 131072;
    if (i < 131072) { int k = i / 256, n = i % 256; w2t[n * 512 + k] = __float2half_rn(W2[i]); return; }
    i -= 131072;
    if (i < 32768)  { int k = i / 128, n = i % 128; blr2[n * 256 + k] = __float2half_rn(Wl2[i]); return; }
    i -= 32768;
    if (i < 32768)  { int k = i / 128, n = i % 128; blr2[(n + 128) * 256 + k] = __float2half_rn(Wr2[i]); return; }
    i -= 32768;
    if (i < 32768)  { int k = i / 256, n = i % 256; w3t[n * 128 + k] = __float2half_rn(W3[i]); return; }
    i -= 32768;
    if (i < 32768)  { int k = i / 128, n = i % 128; w4t[n * 256 + k] = __float2half_rn(W4[i]); }
}

// ---------------- edge scatter: fp16x2 vector-RED, 16 lanes/edge ----------------
__global__ void k_scatter_h(const void* __restrict__ ei, const __half* __restrict__ feat,
                            int fstride, __half* __restrict__ agg, int dstride,
                            float* __restrict__ deg, int addDeg)
{
    int gt   = blockIdx.x * blockDim.x + threadIdx.x;
    int edge = gt >> 4;
    int hl   = gt & 15;
    if (edge >= N_EDGES) return;

    long long s, d;
    if (g_is64) {
        const long long* p = (const long long*)ei;
        s = p[edge]; d = p[N_EDGES + edge];
    } else {
        const int* p = (const int*)ei;
        s = p[edge];  d = p[N_EDGES + edge];
    }

    uint4 v = *reinterpret_cast<const uint4*>(feat + (size_t)s * fstride + hl * 8);
    __half* dp = agg + (size_t)d * dstride + hl * 8;
    asm volatile("red.global.add.noftz.v4.f16x2 [%0], {%1,%2,%3,%4};"
                 :: "l"(dp), "r"(v.x), "r"(v.y), "r"(v.z), "r"(v.w) : "memory");
    if (addDeg && hl == 0) atomicAdd(deg + d, 1.0f);
}

// ---------------- LN+ReLU: per-thread float stats, 8 halves/thread ----------------
__global__ void k_lnrelu(const __half* __restrict__ src, __half* __restrict__ dst,
                         const float* __restrict__ w, const float* __restrict__ b,
                         int Cmask, int statOff, float invcnt, int total8)
{
    int idx = blockIdx.x * blockDim.x + threadIdx.x;
    if (idx >= total8) return;
    float s0 = (float)g_sums[statOff];
    float s1 = (float)g_sums[statOff + 1];
    float mu = s0 * invcnt;
    float rs = rsqrtf(fmaf(s1, invcnt, -mu * mu) + 1e-5f);
    int c = (idx * 8) & Cmask;
    uint4 u = reinterpret_cast<const uint4*>(src)[idx];
    float2 v0 = __half22float2(*reinterpret_cast<const __half2*>(&u.x));
    float2 v1 = __half22float2(*reinterpret_cast<const __half2*>(&u.y));
    float2 v2 = __half22float2(*reinterpret_cast<const __half2*>(&u.z));
    float2 v3 = __half22float2(*reinterpret_cast<const __half2*>(&u.w));
    float4 wa = *reinterpret_cast<const float4*>(w + c);
    float4 wb = *reinterpret_cast<const float4*>(w + c + 4);
    float4 ba = *reinterpret_cast<const float4*>(b + c);
    float4 bb = *reinterpret_cast<const float4*>(b + c + 4);
    __half2 o0 = __floats2half2_rn(fmaxf((v0.x - mu) * rs * wa.x + ba.x, 0.f),
                                   fmaxf((v0.y - mu) * rs * wa.y + ba.y, 0.f));
    __half2 o1 = __floats2half2_rn(fmaxf((v1.x - mu) * rs * wa.z + ba.z, 0.f),
                                   fmaxf((v1.y - mu) * rs * wa.w + ba.w, 0.f));
    __half2 o2 = __floats2half2_rn(fmaxf((v2.x - mu) * rs * wb.x + bb.x, 0.f),
                                   fmaxf((v2.y - mu) * rs * wb.y + bb.y, 0.f));
    __half2 o3 = __floats2half2_rn(fmaxf((v3.x - mu) * rs * wb.z + bb.z, 0.f),
                                   fmaxf((v3.y - mu) * rs * wb.w + bb.w, 0.f));
    uint4 o = make_uint4(*reinterpret_cast<unsigned*>(&o0), *reinterpret_cast<unsigned*>(&o1),
                         *reinterpret_cast<unsigned*>(&o2), *reinterpret_cast<unsigned*>(&o3));
    reinterpret_cast<uint4*>(dst)[idx] = o;
}

// ---------------- FP16 tensor-core GEMM, 3-stage cp.async ring, XOR swizzle ----------------
#define TILE_BYTES (128 * 128)
#define STAGE_BYTES (2 * TILE_BYTES)
#define NSTAGE 3
#define GEMM_SMEM_BYTES (NSTAGE * STAGE_BYTES)

__device__ __forceinline__ void ldsm4(unsigned* r, unsigned addr)
{
    asm volatile("ldmatrix.sync.aligned.m8n8.x4.shared.b16 {%0,%1,%2,%3}, [%4];"
                 : "=r"(r[0]), "=r"(r[1]), "=r"(r[2]), "=r"(r[3]) : "r"(addr));
}

__device__ __forceinline__ void mma_f16(float* c, const unsigned* a,
                                        unsigned b0, unsigned b1)
{
    asm volatile(
        "mma.sync.aligned.m16n8k16.row.col.f32.f16.f16.f32 "
        "{%0,%1,%2,%3}, {%4,%5,%6,%7}, {%8,%9}, {%0,%1,%2,%3};\n"
        : "+f"(c[0]), "+f"(c[1]), "+f"(c[2]), "+f"(c[3])
        : "r"(a[0]), "r"(a[1]), "r"(a[2]), "r"(a[3]), "r"(b0), "r"(b1));
}

template <bool RELU, bool BIAS, bool STATS, bool HOUT, bool MS>
__global__ void __launch_bounds__(256, 2)
k_gemm(const __half* __restrict__ A, const __half* __restrict__ Bt,
       const float* __restrict__ bias, float* __restrict__ C,
       int M, int Nc, int K, double* __restrict__ sums,
       const float* __restrict__ deg)
{
    extern __shared__ __align__(16) unsigned char dsm[];

    const int tid  = threadIdx.x;
    const int lane = tid & 31;
    const int wid  = tid >> 5;
    const int g    = lane >> 2;
    const int t4   = lane & 3;
    const int warpM = (wid >> 2) * 64;
    const int warpN = (wid & 3) * 32;
    const int rowBase = blockIdx.y * 128;
    const int colBase = blockIdx.x * 128;

    float acc[4][4][4];
#pragma unroll
    for (int i = 0; i < 4; i++)
#pragma unroll
        for (int j = 0; j < 4; j++)
#pragma unroll
            for (int k = 0; k < 4; k++) acc[i][j][k] = 0.f;

    float inv0[4], inv8[4];
    if (MS) {
#pragma unroll
        for (int mt = 0; mt < 4; mt++) {
            int r0 = rowBase + warpM + mt * 16 + g;
            inv0[mt] = (r0 < M)     ? 1.0f / fmaxf(deg[r0], 1.0f)     : 1.0f;
            inv8[mt] = (r0 + 8 < M) ? 1.0f / fmaxf(deg[r0 + 8], 1.0f) : 1.0f;
        }
    }

    const int fR  = tid >> 1;
    const int fXr = fR & 7;
    const int fC0 = (tid & 1) * 4;
    const unsigned smBase = (unsigned)__cvta_generic_to_shared(dsm);
    const unsigned aRowDst = smBase + (unsigned)(fR * 128);
    const unsigned bRowDst = smBase + (unsigned)(TILE_BYTES + fR * 128);
    const bool aOk = (rowBase + fR) < M;
    const int  aSz = aOk ? 16 : 0;
    const __half* aSrcRow = A + (size_t)(aOk ? rowBase + fR : 0) * K + fC0 * 8;
    const __half* bSrcRow = Bt + (size_t)(colBase + fR) * K + fC0 * 8;

    const int aRowL = warpM + (lane & 7) + ((lane >> 3) & 1) * 8;
    const unsigned aRow0 = smBase + (unsigned)(aRowL * 128);
    const int xrA = lane & 7;
    const int cA  = (lane >> 4) & 1;
    const int bRowL = warpN + (lane & 7);
    const unsigned bRow0 = smBase + (unsigned)(TILE_BYTES + bRowL * 128);
    const int xrB = lane & 7;
    const int cB  = lane >> 3;

    auto FILL = [&](int s, int k0) {
        unsigned off = (unsigned)(s * STAGE_BYTES);
        const __half* as = aSrcRow + k0;
        const __half* bs = bSrcRow + k0;
#pragma unroll
        for (int j = 0; j < 4; j++) {
            unsigned dA = aRowDst + off + (unsigned)((((fC0 + j) ^ fXr)) << 4);
            asm volatile("cp.async.cg.shared.global [%0], [%1], 16, %2;"
                         :: "r"(dA), "l"(as + j * 8), "r"(aSz) : "memory");
        }
#pragma unroll
        for (int j = 0; j < 4; j++) {
            unsigned dB = bRowDst + off + (unsigned)((((fC0 + j) ^ fXr)) << 4);
            asm volatile("cp.async.cg.shared.global [%0], [%1], 16;"
                         :: "r"(dB), "l"(bs + j * 8) : "memory");
        }
        asm volatile("cp.async.commit_group;" ::: "memory");
    };

    auto MMA = [&](int s) {
        unsigned off = (unsigned)(s * STAGE_BYTES);
#pragma unroll
        for (int kbp = 0; kbp < 2; kbp++) {
            unsigned bf[4][4];
#pragma unroll
            for (int nt = 0; nt < 4; nt++)
                ldsm4(bf[nt], bRow0 + off + (unsigned)(nt * 8 * 128)
                              + (unsigned)(((cB + 4 * kbp) ^ xrB) << 4));
#pragma unroll
            for (int kk = 0; kk < 2; kk++) {
                int kb = kbp * 2 + kk;
                unsigned af[4][4];
#pragma unroll
                for (int mt = 0; mt < 4; mt++)
                    ldsm4(af[mt], aRow0 + off + (unsigned)(mt * 16 * 128)
                                  + (unsigned)(((cA + 2 * kb) ^ xrA) << 4));
#pragma unroll
                for (int nt = 0; nt < 4; nt++)
#pragma unroll
                    for (int mt = 0; mt < 4; mt++)
                        mma_f16(acc[mt][nt], af[mt], bf[nt][kk * 2], bf[nt][kk * 2 + 1]);
            }
        }
    };

    const int T = K >> 6;
    FILL(0, 0);
    if (T > 1) FILL(1, 64);
    int curS = 0;
    int fillS = (T > 1) ? 2 : 1;
    if (fillS >= NSTAGE) fillS -= NSTAGE;
    for (int i = 0; i < T; i++) {
        if (i + 1 < T) { asm volatile("cp.async.wait_group 1;" ::: "memory"); }
        else           { asm volatile("cp.async.wait_group 0;" ::: "memory"); }
        __syncthreads();
        if (i + 2 < T) {
            FILL(fillS, (i + 2) * 64);
            if (++fillS == NSTAGE) fillS = 0;
        }
        MMA(curS);
        if (MS && i == 1) {
#pragma unroll
            for (int mt = 0; mt < 4; mt++)
#pragma unroll
                for (int nt = 0; nt < 4; nt++) {
                    acc[mt][nt][0] *= inv0[mt];
                    acc[mt][nt][1] *= inv0[mt];
                    acc[mt][nt][2] *= inv8[mt];
                    acc[mt][nt][3] *= inv8[mt];
                }
        }
        if (++curS == NSTAGE) curS = 0;
    }

    // ---- epilogue ----
    __half* Ch = reinterpret_cast<__half*>(C);
    float s1 = 0.f, s2 = 0.f;   // per-thread stats (fp32; warp-reduced then atomically summed)
#pragma unroll
    for (int nt = 0; nt < 4; nt++) {
        int col = colBase + warpN + nt * 8 + 2 * t4;
        float2 bv = make_float2(0.f, 0.f);
        if (BIAS) bv = *reinterpret_cast<const float2*>(bias + col);
#pragma unroll
        for (int mt = 0; mt < 4; mt++) {
            int r0 = rowBase + warpM + mt * 16 + g;
            float c0 = acc[mt][nt][0] + bv.x;
            float c1 = acc[mt][nt][1] + bv.y;
            float c2 = acc[mt][nt][2] + bv.x;
            float c3 = acc[mt][nt][3] + bv.y;
            if (RELU) {
                c0 = fmaxf(c0, 0.f); c1 = fmaxf(c1, 0.f);
                c2 = fmaxf(c2, 0.f); c3 = fmaxf(c3, 0.f);
            }
            if (r0 < M) {
                if (HOUT)
                    *reinterpret_cast<__half2*>(Ch + (size_t)r0 * Nc + col) = __floats2half2_rn(c0, c1);
                else
                    *reinterpret_cast<float2*>(C + (size_t)r0 * Nc + col) = make_float2(c0, c1);
                if (STATS) { s1 += c0 + c1; s2 += c0 * c0 + c1 * c1; }
            }
            if (r0 + 8 < M) {
                if (HOUT)
                    *reinterpret_cast<__half2*>(Ch + (size_t)(r0 + 8) * Nc + col) = __floats2half2_rn(c2, c3);
                else
                    *reinterpret_cast<float2*>(C + (size_t)(r0 + 8) * Nc + col) = make_float2(c2, c3);
                if (STATS) { s1 += c2 + c3; s2 += c2 * c2 + c3 * c3; }
            }
        }
    }

    if (STATS) {
        // warp butterfly reduction, then one atomic pair per warp (no barriers)
        double d1 = (double)s1, d2 = (double)s2;
#pragma unroll
        for (int o = 16; o > 0; o >>= 1) {
            d1 += __shfl_xor_sync(0xFFFFFFFFu, d1, o);
            d2 += __shfl_xor_sync(0xFFFFFFFFu, d2, o);
        }
        if (lane == 0) {
            atomicAdd(&sums[0], d1);
            atomicAdd(&sums[1], d2);
        }
    }
}

// ---------------- conv2 combine: 8 halves/thread, warp-shuffle stats ----------------
__global__ void k_y2(const __half* __restrict__ agg216, const __half* __restrict__ pr16,
                     const float* __restrict__ bl2, const float* __restrict__ deg,
                     __half* __restrict__ y2)
{
    float s1 = 0.f, s2 = 0.f;
    const int n8 = N_NODES * 16;
    for (int idx = blockIdx.x * blockDim.x + threadIdx.x; idx < n8; idx += gridDim.x * blockDim.x) {
        int i = idx >> 4, c = (idx & 15) * 8;
        float inv = 1.0f / fmaxf(deg[i], 1.0f);
        uint4 au = *reinterpret_cast<const uint4*>(agg216 + (size_t)i * 128 + c);
        uint4 ru = *reinterpret_cast<const uint4*>(pr16 + (size_t)i * 256 + 128 + c);
        const unsigned* aw = &au.x;
        const unsigned* rw = &ru.x;
        unsigned ow[4];
#pragma unroll
        for (int q = 0; q < 4; q++) {
            float2 a = __half22float2(*reinterpret_cast<const __half2*>(&aw[q]));
            float2 r = __half22float2(*reinterpret_cast<const __half2*>(&rw[q]));
            float2 bq = *reinterpret_cast<const float2*>(bl2 + c + q * 2);
            float y0 = a.x * inv + bq.x + r.x;
            float y1 = a.y * inv + bq.y + r.y;
            __half2 h = __floats2half2_rn(y0, y1);
            ow[q] = *reinterpret_cast<unsigned*>(&h);
            s1 += y0 + y1;
            s2 += y0 * y0 + y1 * y1;
        }
        *reinterpret_cast<uint4*>(y2 + (size_t)i * 128 + c) =
            make_uint4(ow[0], ow[1], ow[2], ow[3]);
    }
    double d1 = (double)s1, d2 = (double)s2;
#pragma unroll
    for (int o = 16; o > 0; o >>= 1) {
        d1 += __shfl_xor_sync(0xFFFFFFFFu, d1, o);
        d2 += __shfl_xor_sync(0xFFFFFFFFu, d2, o);
    }
    if ((threadIdx.x & 31) == 0) {
        atomicAdd(&g_sums[2], d1);
        atomicAdd(&g_sums[3], d2);
    }
}

// ---------------- launch ----------------
extern "C" void kernel_launch(void* const* d_in, const int* in_sizes, int n_in,
                              void* d_out, int out_size)
{
    const float* x    = (const float*)d_in[0];
    const void*  ei   =               d_in[1];
    const float* Wl1  = (const float*)d_in[2];
    const float* bl1  = (const float*)d_in[3];
    const float* Wr1  = (const float*)d_in[4];
    const float* ln1w = (const float*)d_in[5];
    const float* ln1b = (const float*)d_in[6];
    const float* W1   = (const float*)d_in[7];
    const float* b1   = (const float*)d_in[8];
    const float* W2   = (const float*)d_in[9];
    const float* b2   = (const float*)d_in[10];
    const float* Wl2  = (const float*)d_in[11];
    const float* bl2  = (const float*)d_in[12];
    const float* Wr2  = (const float*)d_in[13];
    const float* ln2w = (const float*)d_in[14];
    const float* ln2b = (const float*)d_in[15];
    const float* W3   = (const float*)d_in[16];
    const float* b3   = (const float*)d_in[17];
    const float* W4   = (const float*)d_in[18];
    const float* b4   = (const float*)d_in[19];
    float* out = (float*)d_out;

    float *deg;
    __half *a1, *agg216, *y1, *z1, *t1, *h2, *pr16, *y2, *z2, *t3;
    __half *bt1, *w1t, *w2t, *blr2, *w3t, *w4t;
    double* sums;
    cudaGetSymbolAddress((void**)&a1,     g_a1);
    cudaGetSymbolAddress((void**)&agg216, g_agg216);
    cudaGetSymbolAddress((void**)&deg,  g_deg);
    cudaGetSymbolAddress((void**)&y1,   g_y1);
    cudaGetSymbolAddress((void**)&z1,   g_z1);
    cudaGetSymbolAddress((void**)&t1,   g_t1);
    cudaGetSymbolAddress((void**)&h2,   g_h2);
    cudaGetSymbolAddress((void**)&pr16, g_pr16);
    cudaGetSymbolAddress((void**)&y2,   g_y2);
    cudaGetSymbolAddress((void**)&z2,   g_z2);
    cudaGetSymbolAddress((void**)&t3,   g_t3);
    cudaGetSymbolAddress((void**)&bt1,  g_bt1);
    cudaGetSymbolAddress((void**)&w1t,  g_w1t);
    cudaGetSymbolAddress((void**)&w2t,  g_w2t);
    cudaGetSymbolAddress((void**)&blr2, g_blr2);
    cudaGetSymbolAddress((void**)&w3t,  g_w3t);
    cudaGetSymbolAddress((void**)&w4t,  g_w4t);
    cudaGetSymbolAddress((void**)&sums, g_sums);

    cudaFuncSetAttribute(k_gemm<false, true,  true,  true,  true >, cudaFuncAttributeMaxDynamicSharedMemorySize, GEMM_SMEM_BYTES);
    cudaFuncSetAttribute(k_gemm<true,  true,  false, true,  false>, cudaFuncAttributeMaxDynamicSharedMemorySize, GEMM_SMEM_BYTES);
    cudaFuncSetAttribute(k_gemm<false, false, false, true,  false>, cudaFuncAttributeMaxDynamicSharedMemorySize, GEMM_SMEM_BYTES);
    cudaFuncSetAttribute(k_gemm<false, true,  false, false, false>, cudaFuncAttributeMaxDynamicSharedMemorySize, GEMM_SMEM_BYTES);

    const int M = N_NODES;
    const unsigned gy = (M + 127) / 128;
    const int scatterBlocks = (N_EDGES * 16 + 255) / 256;

    // --- single prep launch ---
    k_prep<<<(PREP_TOTAL + 255) / 256, 256>>>((const unsigned long long*)ei,
                                              x, a1, (uint4*)agg216, (float4*)deg,
                                              Wl1, Wr1, W1, W2, Wl2, Wr2, W3, W4,
                                              bt1, w1t, w2t, blr2, w3t, w4t);

    // --- conv1 ---
    k_scatter_h<<<scatterBlocks, 256>>>(ei, a1 + 128, 256, a1, 256, deg, 1);
    k_gemm<false, true, true, true, true><<<dim3(2, gy), 256, GEMM_SMEM_BYTES>>>(
        a1, bt1, bl1, (float*)y1, M, 256, 256, sums, deg);
    k_lnrelu<<<(N_NODES * 32 + 255) / 256, 256>>>(y1, z1, ln1w, ln1b, 255, 0,
                                                  1.0f / (float)(N_NODES * 256.0), N_NODES * 32);
    k_gemm<true, true, false, true, false><<<dim3(4, gy), 256, GEMM_SMEM_BYTES>>>(
        z1, w1t, b1, (float*)t1, M, 512, 256, nullptr, nullptr);
    k_gemm<true, true, false, true, false><<<dim3(2, gy), 256, GEMM_SMEM_BYTES>>>(
        t1, w2t, b2, (float*)h2, M, 256, 512, nullptr, nullptr);

    // --- conv2 ---
    k_gemm<false, false, false, true, false><<<dim3(2, gy), 256, GEMM_SMEM_BYTES>>>(
        h2, blr2, nullptr, (float*)pr16, M, 256, 256, nullptr, nullptr);
    k_scatter_h<<<scatterBlocks, 256>>>(ei, pr16, 256, agg216, 128, deg, 0);
    k_y2<<<1024, 256>>>(agg216, pr16, bl2, deg, y2);
    k_lnrelu<<<(N_NODES * 16 + 255) / 256, 256>>>(y2, z2, ln2w, ln2b, 127, 2,
                                                  1.0f / (float)(N_NODES * 128.0), N_NODES * 16);
    k_gemm<true, true, false, true, false><<<dim3(2, gy), 256, GEMM_SMEM_BYTES>>>(
        z2, w3t, b3, (float*)t3, M, 256, 128, nullptr, nullptr);
    k_gemm<false, true, false, false, false><<<dim3(1, gy), 256, GEMM_SMEM_BYTES>>>(
        t3, w4t, b4, out, M, 128, 256, nullptr, nullptr);
}